// round 2
// baseline (speedup 1.0000x reference)
#include <cuda_runtime.h>
#include <math.h>

#define Bsz 2
#define Lq  4096
#define Dm  512
#define Hn  8
#define HD  64

// Scratch (device globals — no allocation allowed)
__device__ float g_q[Bsz*Hn*HD*Lq];   // [b][h][d][l], pre-scaled by 1/sqrt(HD)
__device__ float g_k[Bsz*Hn*HD*Lq];   // [b][h][d][l]   (K transposed for coalesced [d][j] tiles)
__device__ float g_v[(size_t)Bsz*Hn*Lq*HD];   // [b][h][l][d]
__device__ float g_o[(size_t)Bsz*Lq*Dm];      // [b][l][h*HD+d]

// ---------------------------------------------------------------------------
// Kernel 1: QKV projection. M=8192, N=1536, K=512.  BM=128, BN=64, BK=16.
// Each 64-wide n-tile maps entirely to one of Q/K/V of one head.
// ---------------------------------------------------------------------------
__global__ __launch_bounds__(256) void qkv_gemm_kernel(
    const float* __restrict__ x, const float* __restrict__ w,
    const float* __restrict__ bias)
{
    __shared__ float As[16][132];
    __shared__ float Bs[16][68];
    const int m0 = blockIdx.y * 128;
    const int n0 = blockIdx.x * 64;
    const int tid = threadIdx.x;
    const int tx = tid & 15, ty = tid >> 4;

    float acc[8][4] = {};
    for (int k0 = 0; k0 < Dm; k0 += 16) {
        #pragma unroll
        for (int p = 0; p < 2; p++) {
            int idx = p*256 + tid;
            int r = idx >> 2;
            int c4 = (idx & 3) * 4;
            float4 a = *(const float4*)(x + (size_t)(m0+r)*Dm + k0 + c4);
            As[c4+0][r]=a.x; As[c4+1][r]=a.y; As[c4+2][r]=a.z; As[c4+3][r]=a.w;
        }
        {
            int r  = tid >> 4;
            int c4 = (tid & 15) * 4;
            *(float4*)&Bs[r][c4] = *(const float4*)(w + (size_t)(k0+r)*(3*Dm) + n0 + c4);
        }
        __syncthreads();
        #pragma unroll
        for (int kk = 0; kk < 16; kk++) {
            float a[8], bb[4];
            *(float4*)&a[0] = *(const float4*)&As[kk][ty*8];
            *(float4*)&a[4] = *(const float4*)&As[kk][ty*8+4];
            *(float4*)&bb[0] = *(const float4*)&Bs[kk][tx*4];
            #pragma unroll
            for (int i = 0; i < 8; i++)
                #pragma unroll
                for (int j = 0; j < 4; j++)
                    acc[i][j] = fmaf(a[i], bb[j], acc[i][j]);
        }
        __syncthreads();
    }

    const int h   = n0 / 192;           // head
    const int sec = (n0 / 64) % 3;      // 0=Q, 1=K, 2=V
    float4 b4 = *(const float4*)(bias + n0 + tx*4);
    float bv[4] = {b4.x, b4.y, b4.z, b4.w};

    #pragma unroll
    for (int i = 0; i < 8; i++) {
        int m    = m0 + ty*8 + i;
        int bidx = m >> 12;             // / Lq
        int l    = m & (Lq-1);
        if (sec == 2) {
            float4 o4;
            o4.x = acc[i][0]+bv[0]; o4.y = acc[i][1]+bv[1];
            o4.z = acc[i][2]+bv[2]; o4.w = acc[i][3]+bv[3];
            *(float4*)(g_v + ((size_t)(bidx*Hn+h)*Lq + l)*HD + tx*4) = o4;
        } else {
            float  scale = (sec == 0) ? 0.125f : 1.0f;   // 1/sqrt(64) folded into Q
            float* dst   = (sec == 0) ? g_q : g_k;
            #pragma unroll
            for (int j = 0; j < 4; j++) {
                int d = tx*4 + j;
                dst[((size_t)(bidx*Hn+h)*HD + d)*Lq + l] = (acc[i][j]+bv[j])*scale;
            }
        }
    }
}

// ---------------------------------------------------------------------------
// Kernel 2: flash attention. grid=(L/64, B*H), 256 threads, Br=Bc=64, HD=64.
// Smem: Qs[d][i] + (Ks[d][j] aliased with Ps[i][j]) + Vs[j][d] = 48 KB exactly.
// ---------------------------------------------------------------------------
__global__ __launch_bounds__(256) void flash_kernel()
{
    __shared__ float Qs[64][64];
    __shared__ float KPs[64][64];
    __shared__ float Vs[64][64];
    const int bh = blockIdx.y;
    const int i0 = blockIdx.x * 64;
    const int tid = threadIdx.x;
    const int tx = tid & 15, ty = tid >> 4;
    const float* qb = g_q + (size_t)bh*HD*Lq;
    const float* kb = g_k + (size_t)bh*HD*Lq;
    const float* vb = g_v + (size_t)bh*Lq*HD;

    #pragma unroll
    for (int p = 0; p < 4; p++) {
        int idx = p*256 + tid;
        int d  = idx >> 4;
        int c4 = (idx & 15) * 4;
        *(float4*)&Qs[d][c4] = *(const float4*)(qb + (size_t)d*Lq + i0 + c4);
    }

    float m_run[4], l_run[4], o[4][4];
    #pragma unroll
    for (int r = 0; r < 4; r++) {
        m_run[r] = -1e30f; l_run[r] = 0.f;
        #pragma unroll
        for (int c = 0; c < 4; c++) o[r][c] = 0.f;
    }

    for (int j0 = 0; j0 < Lq; j0 += 64) {
        #pragma unroll
        for (int p = 0; p < 4; p++) {
            int idx = p*256 + tid;
            int a  = idx >> 4;
            int c4 = (idx & 15) * 4;
            *(float4*)&KPs[a][c4] = *(const float4*)(kb + (size_t)a*Lq + j0 + c4);
            *(float4*)&Vs[a][c4]  = *(const float4*)(vb + (size_t)(j0+a)*HD + c4);
        }
        __syncthreads();

        // S = (Q*scale) K^T : 4x4 microtile per thread
        float s[4][4] = {};
        #pragma unroll
        for (int d = 0; d < 64; d++) {
            float q4[4], k4[4];
            *(float4*)q4 = *(const float4*)&Qs[d][ty*4];
            *(float4*)k4 = *(const float4*)&KPs[d][tx*4];
            #pragma unroll
            for (int r = 0; r < 4; r++)
                #pragma unroll
                for (int c = 0; c < 4; c++)
                    s[r][c] = fmaf(q4[r], k4[c], s[r][c]);
        }

        // online softmax (rows distributed over 16 lanes sharing ty)
        float alpha[4];
        #pragma unroll
        for (int r = 0; r < 4; r++) {
            float mt = fmaxf(fmaxf(s[r][0], s[r][1]), fmaxf(s[r][2], s[r][3]));
            #pragma unroll
            for (int off = 8; off >= 1; off >>= 1)
                mt = fmaxf(mt, __shfl_xor_sync(0xffffffffu, mt, off));
            mt = fmaxf(mt, m_run[r]);
            alpha[r] = __expf(m_run[r] - mt);
            m_run[r] = mt;
            float p0 = __expf(s[r][0]-mt), p1 = __expf(s[r][1]-mt);
            float p2 = __expf(s[r][2]-mt), p3 = __expf(s[r][3]-mt);
            s[r][0]=p0; s[r][1]=p1; s[r][2]=p2; s[r][3]=p3;
            float ps = p0+p1+p2+p3;
            #pragma unroll
            for (int off = 8; off >= 1; off >>= 1)
                ps += __shfl_xor_sync(0xffffffffu, ps, off);
            l_run[r] = l_run[r]*alpha[r] + ps;
            #pragma unroll
            for (int c = 0; c < 4; c++) o[r][c] *= alpha[r];
        }
        __syncthreads();                       // done reading K tile

        // P -> smem (reuse K tile storage), natural [i][j] layout
        #pragma unroll
        for (int r = 0; r < 4; r++)
            *(float4*)&KPs[ty*4+r][tx*4] = make_float4(s[r][0], s[r][1], s[r][2], s[r][3]);
        __syncthreads();

        // O += P @ V
        #pragma unroll 8
        for (int j = 0; j < 64; j++) {
            float v4[4];
            *(float4*)v4 = *(const float4*)&Vs[j][tx*4];
            #pragma unroll
            for (int r = 0; r < 4; r++) {
                float pv = KPs[ty*4+r][j];     // broadcast read, conflict-free
                #pragma unroll
                for (int c = 0; c < 4; c++)
                    o[r][c] = fmaf(pv, v4[c], o[r][c]);
            }
        }
        __syncthreads();                       // before next tile overwrites
    }

    const int b = bh >> 3, h = bh & 7;
    #pragma unroll
    for (int r = 0; r < 4; r++) {
        float inv = 1.0f / l_run[r];
        float4 o4 = make_float4(o[r][0]*inv, o[r][1]*inv, o[r][2]*inv, o[r][3]*inv);
        int row = i0 + ty*4 + r;
        *(float4*)(g_o + ((size_t)b*Lq + row)*Dm + h*HD + tx*4) = o4;
    }
}

// ---------------------------------------------------------------------------
// Kernel 3: output projection. M=8192, N=512, K=512. Same tiling.
// ---------------------------------------------------------------------------
__global__ __launch_bounds__(256) void out_gemm_kernel(
    const float* __restrict__ w, const float* __restrict__ bias,
    float* __restrict__ out)
{
    __shared__ float As[16][132];
    __shared__ float Bs[16][68];
    const int m0 = blockIdx.y * 128;
    const int n0 = blockIdx.x * 64;
    const int tid = threadIdx.x;
    const int tx = tid & 15, ty = tid >> 4;

    float acc[8][4] = {};
    for (int k0 = 0; k0 < Dm; k0 += 16) {
        #pragma unroll
        for (int p = 0; p < 2; p++) {
            int idx = p*256 + tid;
            int r = idx >> 2;
            int c4 = (idx & 3) * 4;
            float4 a = *(const float4*)(g_o + (size_t)(m0+r)*Dm + k0 + c4);
            As[c4+0][r]=a.x; As[c4+1][r]=a.y; As[c4+2][r]=a.z; As[c4+3][r]=a.w;
        }
        {
            int r  = tid >> 4;
            int c4 = (tid & 15) * 4;
            *(float4*)&Bs[r][c4] = *(const float4*)(w + (size_t)(k0+r)*Dm + n0 + c4);
        }
        __syncthreads();
        #pragma unroll
        for (int kk = 0; kk < 16; kk++) {
            float a[8], bb[4];
            *(float4*)&a[0] = *(const float4*)&As[kk][ty*8];
            *(float4*)&a[4] = *(const float4*)&As[kk][ty*8+4];
            *(float4*)&bb[0] = *(const float4*)&Bs[kk][tx*4];
            #pragma unroll
            for (int i = 0; i < 8; i++)
                #pragma unroll
                for (int j = 0; j < 4; j++)
                    acc[i][j] = fmaf(a[i], bb[j], acc[i][j]);
        }
        __syncthreads();
    }

    float4 b4 = *(const float4*)(bias + n0 + tx*4);
    #pragma unroll
    for (int i = 0; i < 8; i++) {
        int m = m0 + ty*8 + i;
        float4 o4;
        o4.x = acc[i][0]+b4.x; o4.y = acc[i][1]+b4.y;
        o4.z = acc[i][2]+b4.z; o4.w = acc[i][3]+b4.w;
        *(float4*)(out + (size_t)m*Dm + n0 + tx*4) = o4;
    }
}

extern "C" void kernel_launch(void* const* d_in, const int* in_sizes, int n_in,
                              void* d_out, int out_size)
{
    const float* x     = (const float*)d_in[0];
    const float* w_qkv = (const float*)d_in[1];
    const float* b_qkv = (const float*)d_in[2];
    const float* w_o   = (const float*)d_in[3];
    const float* b_o   = (const float*)d_in[4];
    float* out = (float*)d_out;

    dim3 g1(3*Dm/64, (Bsz*Lq)/128);   // (24, 64)
    qkv_gemm_kernel<<<g1, 256>>>(x, w_qkv, b_qkv);

    dim3 g2(Lq/64, Bsz*Hn);           // (64, 16)
    flash_kernel<<<g2, 256>>>();

    dim3 g3(Dm/64, (Bsz*Lq)/128);     // (8, 64)
    out_gemm_kernel<<<g3, 256>>>(w_o, b_o, out);
}

// round 8
// speedup vs baseline: 1.6695x; 1.6695x over previous
#include <cuda_runtime.h>
#include <math.h>
#include <stdint.h>

#define Bsz 2
#define Lq  4096
#define Dm  512
#define Hn  8
#define HD  64

// Scratch (device globals — allocation is forbidden)
__device__ float g_q[(size_t)Bsz*Hn*HD*Lq];   // [b][h][d][l], pre-scaled by 1/8, tf32-rounded
__device__ float g_k[(size_t)Bsz*Hn*HD*Lq];   // [b][h][d][l], tf32-rounded
__device__ float g_v[(size_t)Bsz*Hn*Lq*HD];   // [b][h][l][d], tf32-rounded
__device__ float g_o[(size_t)Bsz*Lq*Dm];      // [b][l][h*HD+d], fp32

__device__ __forceinline__ uint32_t f2t(float f) {
    uint32_t u; asm("cvt.rna.tf32.f32 %0, %1;" : "=r"(u) : "f"(f)); return u;
}

// D += A(16x8 tf32) * B(8x8 tf32), fp32 accum.
// CUTLASS SM80_16x8x8_F32TF32TF32F32_TN verified fragment layout
// (g=lane>>2, t4=lane&3):
//   a0=(g,t4) a1=(g+8,t4) a2=(g,t4+4) a3=(g+8,t4+4)
//   b0=(t4,g) b1=(t4+4,g)
//   c0=(g,2t4) c1=(g,2t4+1) c2=(g+8,2t4) c3=(g+8,2t4+1)
__device__ __forceinline__ void mma8(float d[4], const uint32_t a[4], const uint32_t b[2]) {
    asm volatile(
        "mma.sync.aligned.m16n8k8.row.col.f32.tf32.tf32.f32 "
        "{%0,%1,%2,%3},{%4,%5,%6,%7},{%8,%9},{%0,%1,%2,%3};\n"
        : "+f"(d[0]), "+f"(d[1]), "+f"(d[2]), "+f"(d[3])
        : "r"(a[0]), "r"(a[1]), "r"(a[2]), "r"(a[3]), "r"(b[0]), "r"(b[1]));
}

#define ASTR 20
#define BSTR 136

// ---------------------------------------------------------------------------
// Shared GEMM core: C[128x128] tile, 256 threads (8 warps: 4 in M x 2 in N),
// warp tile 32x64 (2 m-tiles x 8 n-tiles of 16x8), BK=16 (2 k-steps of 8).
// As [m][k] stride 20 (scalar A-frag loads: banks 20g+t4, conflict-free),
// Bs [k][n] stride 136 (scalar B-frag loads: banks 8t4+g, conflict-free).
// Static smem: (128*20 + 16*136)*4 = 18944 B.
// ---------------------------------------------------------------------------
__device__ __forceinline__ void gemm_core(
    const float* __restrict__ A, const float* __restrict__ Bw,
    int lda, int ldb, int m0, int n0,
    float (*acc)[8][4], float* As, float* Bs)
{
    const int tid = threadIdx.x;
    const int lane = tid & 31;
    const int g = lane >> 2, t4 = lane & 3;
    const int w = tid >> 5;
    const int wm = w & 3, wn = w >> 2;
    const uint32_t* asp = (const uint32_t*)As;
    const uint32_t* bsp = (const uint32_t*)Bs;

    for (int k0 = 0; k0 < Dm; k0 += 16) {
        #pragma unroll
        for (int p = 0; p < 2; p++) {       // A tile 128x16
            int idx = p*256 + tid;
            int m = idx >> 2, c = (idx & 3) * 4;
            float4 v = *(const float4*)(A + (size_t)(m0+m)*lda + k0 + c);
            uint4 u = make_uint4(f2t(v.x), f2t(v.y), f2t(v.z), f2t(v.w));
            *(uint4*)(As + m*ASTR + c) = u;
        }
        #pragma unroll
        for (int p = 0; p < 2; p++) {       // B tile 16x128
            int idx = p*256 + tid;
            int kk = idx >> 5, c = (idx & 31) * 4;
            float4 v = *(const float4*)(Bw + (size_t)(k0+kk)*ldb + n0 + c);
            uint4 u = make_uint4(f2t(v.x), f2t(v.y), f2t(v.z), f2t(v.w));
            *(uint4*)(Bs + kk*BSTR + c) = u;
        }
        __syncthreads();

        #pragma unroll
        for (int kc = 0; kc < 2; kc++) {
            uint32_t af[2][4];
            #pragma unroll
            for (int mt = 0; mt < 2; mt++) {
                int mr = 32*wm + 16*mt + g;
                af[mt][0] = asp[(mr  )*ASTR + 8*kc + t4];
                af[mt][1] = asp[(mr+8)*ASTR + 8*kc + t4];
                af[mt][2] = asp[(mr  )*ASTR + 8*kc + t4 + 4];
                af[mt][3] = asp[(mr+8)*ASTR + 8*kc + t4 + 4];
            }
            #pragma unroll
            for (int nt = 0; nt < 8; nt++) {
                uint32_t bf[2];
                bf[0] = bsp[(8*kc+t4  )*BSTR + 64*wn + 8*nt + g];
                bf[1] = bsp[(8*kc+t4+4)*BSTR + 64*wn + 8*nt + g];
                mma8(acc[0][nt], af[0], bf);
                mma8(acc[1][nt], af[1], bf);
            }
        }
        __syncthreads();
    }
}

// ---------------------------------------------------------------------------
// Kernel 1: QKV projection. M=8192, N=1536, K=512. grid (12, 64).
// ---------------------------------------------------------------------------
__global__ __launch_bounds__(256) void qkv_gemm_kernel(
    const float* __restrict__ x, const float* __restrict__ wqkv,
    const float* __restrict__ bias)
{
    __shared__ float As[128*ASTR];
    __shared__ float Bs[16*BSTR];
    const int m0 = blockIdx.y * 128;
    const int n0 = blockIdx.x * 128;
    const int tid = threadIdx.x;
    const int lane = tid & 31;
    const int g = lane >> 2, t4 = lane & 3;
    const int w = tid >> 5;
    const int wm = w & 3, wn = w >> 2;

    float acc[2][8][4] = {};
    gemm_core(x, wqkv, Dm, 3*Dm, m0, n0, acc, As, Bs);

    const int nbase = n0 + 64*wn;
    const int h   = nbase / 192;
    const int sec = (nbase >> 6) % 3;       // 0=Q 1=K 2=V

    #pragma unroll
    for (int mt = 0; mt < 2; mt++) {
        #pragma unroll
        for (int rr = 0; rr < 2; rr++) {
            int m = m0 + 32*wm + 16*mt + g + 8*rr;
            int b = m >> 12, l = m & (Lq-1);
            #pragma unroll
            for (int nt = 0; nt < 8; nt++) {
                int nn = nbase + 8*nt + 2*t4;
                float v0 = acc[mt][nt][2*rr+0] + bias[nn];
                float v1 = acc[mt][nt][2*rr+1] + bias[nn+1];
                int d0 = nn & 63;
                if (sec == 2) {
                    float2 o2;
                    o2.x = __uint_as_float(f2t(v0));
                    o2.y = __uint_as_float(f2t(v1));
                    *(float2*)(g_v + ((size_t)(b*Hn+h)*Lq + l)*HD + d0) = o2;
                } else {
                    float sc = (sec == 0) ? 0.125f : 1.0f;
                    float* dst = (sec == 0) ? g_q : g_k;
                    dst[((size_t)(b*Hn+h)*HD + d0  )*Lq + l] = __uint_as_float(f2t(v0*sc));
                    dst[((size_t)(b*Hn+h)*HD + d0+1)*Lq + l] = __uint_as_float(f2t(v1*sc));
                }
            }
        }
    }
}

// ---------------------------------------------------------------------------
// Kernel 2: flash attention with TF32 mma. grid (64, 16), 128 threads.
// Br=Bc=64, HD=64. Each warp: 16 rows x full 64 cols (no cross-warp softmax).
// STATIC smem: Ks/Vs/Ps 64x64 each = 49152 B exactly (no opt-in needed).
// XOR swizzle SWZ(r,c)=c^((r&3)<<3) gives conflict-free K/V/Q fragment reads.
// Q tile staged through Ks region before the KV loop.
// ---------------------------------------------------------------------------
#define SWZ(r, c) ((c) ^ (((r) & 3) << 3))

__global__ __launch_bounds__(128) void flash_kernel()
{
    __shared__ float Ks[64*64];
    __shared__ float Vs[64*64];
    __shared__ float Ps[64*64];
    const int bh = blockIdx.y;
    const int i0 = blockIdx.x * 64;
    const int tid = threadIdx.x;
    const int w = tid >> 5, lane = tid & 31;
    const int g = lane >> 2, t4 = lane & 3;
    const float* qb = g_q + (size_t)bh*HD*Lq;
    const float* kb = g_k + (size_t)bh*HD*Lq;
    const float* vb = g_v + (size_t)bh*Lq*HD;

    // Stage Q tile [d][i] (swizzled) into Ks region, hoist fragments.
    #pragma unroll
    for (int p = 0; p < 8; p++) {
        int idx = p*128 + tid;
        int d = idx >> 4, c = (idx & 15) * 4;
        *(float4*)&Ks[d*64 + SWZ(d, c)] = *(const float4*)(qb + (size_t)d*Lq + i0 + c);
    }
    __syncthreads();
    uint32_t qf[8][4];
    {
        const uint32_t* ksu = (const uint32_t*)Ks;
        int col = 16*w + g;
        #pragma unroll
        for (int ks = 0; ks < 8; ks++) {
            int r0 = 8*ks + t4, r1 = r0 + 4;
            qf[ks][0] = ksu[r0*64 + SWZ(r0, col)];
            qf[ks][1] = ksu[r0*64 + SWZ(r0, col+8)];
            qf[ks][2] = ksu[r1*64 + SWZ(r1, col)];
            qf[ks][3] = ksu[r1*64 + SWZ(r1, col+8)];
        }
    }

    float of[8][4] = {};
    float mlo = -1e30f, mhi = -1e30f, llo = 0.f, lhi = 0.f;
    const uint32_t* ksu = (const uint32_t*)Ks;
    const uint32_t* vsu = (const uint32_t*)Vs;
    uint32_t* pw = (uint32_t*)Ps;
    const int row_lo = 16*w + g, row_hi = row_lo + 8;

    for (int j0 = 0; j0 < Lq; j0 += 64) {
        __syncthreads();                     // Ks (Q staging / prev K) reads done
        // FULL 64-row tiles: 8*128 = 1024 float4 stores per array (was p<4 — the bug)
        #pragma unroll
        for (int p = 0; p < 8; p++) {
            int idx = p*128 + tid;
            int a = idx >> 4, c = (idx & 15) * 4;
            *(float4*)&Ks[a*64 + SWZ(a, c)] = *(const float4*)(kb + (size_t)a*Lq + j0 + c);
            *(float4*)&Vs[a*64 + SWZ(a, c)] = *(const float4*)(vb + (size_t)(j0+a)*HD + c);
        }
        __syncthreads();

        // S = Q K^T (16x64 per warp)
        float s[8][4] = {};
        #pragma unroll
        for (int ks = 0; ks < 8; ks++) {
            int r0 = 8*ks + t4, r1 = r0 + 4;
            #pragma unroll
            for (int nt = 0; nt < 8; nt++) {
                uint32_t bf[2];
                bf[0] = ksu[r0*64 + SWZ(r0, 8*nt + g)];
                bf[1] = ksu[r1*64 + SWZ(r1, 8*nt + g)];
                mma8(s[nt], qf[ks], bf);
            }
        }

        // Online softmax: row_lo holds (c0,c1), row_hi holds (c2,c3); quad-reduce.
        float mxl = -1e30f, mxh = -1e30f;
        #pragma unroll
        for (int nt = 0; nt < 8; nt++) {
            mxl = fmaxf(mxl, fmaxf(s[nt][0], s[nt][1]));
            mxh = fmaxf(mxh, fmaxf(s[nt][2], s[nt][3]));
        }
        mxl = fmaxf(mxl, __shfl_xor_sync(0xffffffffu, mxl, 1));
        mxl = fmaxf(mxl, __shfl_xor_sync(0xffffffffu, mxl, 2));
        mxh = fmaxf(mxh, __shfl_xor_sync(0xffffffffu, mxh, 1));
        mxh = fmaxf(mxh, __shfl_xor_sync(0xffffffffu, mxh, 2));
        float mnl = fmaxf(mxl, mlo), mnh = fmaxf(mxh, mhi);
        float al = __expf(mlo - mnl), ah = __expf(mhi - mnh);
        mlo = mnl; mhi = mnh;
        float sl = 0.f, sh = 0.f;
        #pragma unroll
        for (int nt = 0; nt < 8; nt++) {
            s[nt][0] = __expf(s[nt][0] - mnl);
            s[nt][1] = __expf(s[nt][1] - mnl);
            s[nt][2] = __expf(s[nt][2] - mnh);
            s[nt][3] = __expf(s[nt][3] - mnh);
            sl += s[nt][0] + s[nt][1];
            sh += s[nt][2] + s[nt][3];
        }
        sl += __shfl_xor_sync(0xffffffffu, sl, 1);
        sl += __shfl_xor_sync(0xffffffffu, sl, 2);
        sh += __shfl_xor_sync(0xffffffffu, sh, 1);
        sh += __shfl_xor_sync(0xffffffffu, sh, 2);
        llo = llo*al + sl; lhi = lhi*ah + sh;
        #pragma unroll
        for (int nt = 0; nt < 8; nt++) {
            of[nt][0] *= al; of[nt][1] *= al;
            of[nt][2] *= ah; of[nt][3] *= ah;
        }

        // P -> warp-private smem rows (tf32), swizzled uint2 (conflict-free)
        #pragma unroll
        for (int nt = 0; nt < 8; nt++) {
            uint2 lo = make_uint2(f2t(s[nt][0]), f2t(s[nt][1]));
            uint2 hi = make_uint2(f2t(s[nt][2]), f2t(s[nt][3]));
            *(uint2*)&pw[row_lo*64 + SWZ(row_lo, 8*nt + 2*t4)] = lo;
            *(uint2*)&pw[row_hi*64 + SWZ(row_hi, 8*nt + 2*t4)] = hi;
        }
        __syncwarp();

        // O += P @ V
        #pragma unroll
        for (int ks = 0; ks < 8; ks++) {
            uint32_t pf[4];
            pf[0] = pw[row_lo*64 + SWZ(row_lo, 8*ks + t4)];
            pf[1] = pw[row_hi*64 + SWZ(row_hi, 8*ks + t4)];
            pf[2] = pw[row_lo*64 + SWZ(row_lo, 8*ks + t4 + 4)];
            pf[3] = pw[row_hi*64 + SWZ(row_hi, 8*ks + t4 + 4)];
            int r0 = 8*ks + t4, r1 = r0 + 4;
            #pragma unroll
            for (int nt = 0; nt < 8; nt++) {
                uint32_t bf[2];
                bf[0] = vsu[r0*64 + SWZ(r0, 8*nt + g)];
                bf[1] = vsu[r1*64 + SWZ(r1, 8*nt + g)];
                mma8(of[nt], pf, bf);
            }
        }
        __syncwarp();
    }

    const int b = bh >> 3, h = bh & 7;
    float il = 1.0f/llo, ih = 1.0f/lhi;
    int rlo = i0 + row_lo, rhi = i0 + row_hi;
    #pragma unroll
    for (int nt = 0; nt < 8; nt++) {
        int d0 = h*64 + 8*nt + 2*t4;
        *(float2*)(g_o + ((size_t)b*Lq + rlo)*Dm + d0) = make_float2(of[nt][0]*il, of[nt][1]*il);
        *(float2*)(g_o + ((size_t)b*Lq + rhi)*Dm + d0) = make_float2(of[nt][2]*ih, of[nt][3]*ih);
    }
}

// ---------------------------------------------------------------------------
// Kernel 3: output projection. M=8192, N=512, K=512. grid (4, 64).
// ---------------------------------------------------------------------------
__global__ __launch_bounds__(256) void out_gemm_kernel(
    const float* __restrict__ wo, const float* __restrict__ bias,
    float* __restrict__ out)
{
    __shared__ float As[128*ASTR];
    __shared__ float Bs[16*BSTR];
    const int m0 = blockIdx.y * 128;
    const int n0 = blockIdx.x * 128;
    const int tid = threadIdx.x;
    const int lane = tid & 31;
    const int g = lane >> 2, t4 = lane & 3;
    const int w = tid >> 5;
    const int wm = w & 3, wn = w >> 2;

    float acc[2][8][4] = {};
    gemm_core(g_o, wo, Dm, Dm, m0, n0, acc, As, Bs);

    #pragma unroll
    for (int mt = 0; mt < 2; mt++) {
        #pragma unroll
        for (int rr = 0; rr < 2; rr++) {
            int m = m0 + 32*wm + 16*mt + g + 8*rr;
            #pragma unroll
            for (int nt = 0; nt < 8; nt++) {
                int n = n0 + 64*wn + 8*nt + 2*t4;
                float2 o2;
                o2.x = acc[mt][nt][2*rr+0] + bias[n];
                o2.y = acc[mt][nt][2*rr+1] + bias[n+1];
                *(float2*)(out + (size_t)m*Dm + n) = o2;
            }
        }
    }
}

extern "C" void kernel_launch(void* const* d_in, const int* in_sizes, int n_in,
                              void* d_out, int out_size)
{
    const float* x     = (const float*)d_in[0];
    const float* w_qkv = (const float*)d_in[1];
    const float* b_qkv = (const float*)d_in[2];
    const float* w_o   = (const float*)d_in[3];
    const float* b_o   = (const float*)d_in[4];
    float* out = (float*)d_out;

    dim3 g1(3*Dm/128, (Bsz*Lq)/128);   // (12, 64)
    qkv_gemm_kernel<<<g1, 256>>>(x, w_qkv, b_qkv);

    dim3 g2(Lq/64, Bsz*Hn);            // (64, 16)
    flash_kernel<<<g2, 128>>>();

    dim3 g3(Dm/128, (Bsz*Lq)/128);     // (4, 64)
    out_gemm_kernel<<<g3, 256>>>(w_o, b_o, out);
}

// round 9
// speedup vs baseline: 2.7524x; 1.6487x over previous
#include <cuda_runtime.h>
#include <math.h>
#include <stdint.h>

#define Bsz 2
#define Lq  4096
#define Dm  512
#define Hn  8
#define HD  64

// Scratch (device globals — allocation is forbidden)
__device__ float g_q[(size_t)Bsz*Hn*Lq*HD];   // [b][h][l][d], pre-scaled by 1/8, tf32-rounded
__device__ float g_k[(size_t)Bsz*Hn*Lq*HD];   // [b][h][l][d], tf32-rounded
__device__ float g_v[(size_t)Bsz*Hn*HD*Lq];   // [b][h][d][l]  (transposed), tf32-rounded
__device__ float g_o[(size_t)Bsz*Lq*Dm];      // [b][l][h*HD+d], fp32

__device__ __forceinline__ uint32_t f2t(float f) {
    uint32_t u; asm("cvt.rna.tf32.f32 %0, %1;" : "=r"(u) : "f"(f)); return u;
}

// D += A(16x8 tf32) * B(8x8 tf32), fp32 accum.
// CUTLASS SM80_16x8x8_F32TF32TF32F32_TN fragment layout (g=lane>>2, t4=lane&3):
//   a0=(g,t4) a1=(g+8,t4) a2=(g,t4+4) a3=(g+8,t4+4)
//   b0=(t4,g) b1=(t4+4,g)
//   c0=(g,2t4) c1=(g,2t4+1) c2=(g+8,2t4) c3=(g+8,2t4+1)
__device__ __forceinline__ void mma8(float d[4], const uint32_t a[4], const uint32_t b[2]) {
    asm volatile(
        "mma.sync.aligned.m16n8k8.row.col.f32.tf32.tf32.f32 "
        "{%0,%1,%2,%3},{%4,%5,%6,%7},{%8,%9},{%0,%1,%2,%3};\n"
        : "+f"(d[0]), "+f"(d[1]), "+f"(d[2]), "+f"(d[3])
        : "r"(a[0]), "r"(a[1]), "r"(a[2]), "r"(a[3]), "r"(b[0]), "r"(b[1]));
}

// ldmatrix x4: 4 8x(16B) matrices; per-lane address selects a 16B row.
__device__ __forceinline__ void ldsm4(uint32_t* f, uint32_t addr) {
    asm volatile(
        "ldmatrix.sync.aligned.m8n8.x4.shared.b16 {%0,%1,%2,%3}, [%4];\n"
        : "=r"(f[0]), "=r"(f[1]), "=r"(f[2]), "=r"(f[3]) : "r"(addr));
}

__device__ __forceinline__ uint32_t smem_u32(const void* p) {
    return (uint32_t)__cvta_generic_to_shared(p);
}

#define ASTR 20
#define BSTR 136

// ---------------------------------------------------------------------------
// Shared GEMM core (unchanged from round 8): C[128x128], 256 threads, 8 warps.
// ---------------------------------------------------------------------------
__device__ __forceinline__ void gemm_core(
    const float* __restrict__ A, const float* __restrict__ Bw,
    int lda, int ldb, int m0, int n0,
    float (*acc)[8][4], float* As, float* Bs)
{
    const int tid = threadIdx.x;
    const int lane = tid & 31;
    const int g = lane >> 2, t4 = lane & 3;
    const int w = tid >> 5;
    const int wm = w & 3, wn = w >> 2;
    const uint32_t* asp = (const uint32_t*)As;
    const uint32_t* bsp = (const uint32_t*)Bs;

    for (int k0 = 0; k0 < Dm; k0 += 16) {
        #pragma unroll
        for (int p = 0; p < 2; p++) {       // A tile 128x16
            int idx = p*256 + tid;
            int m = idx >> 2, c = (idx & 3) * 4;
            float4 v = *(const float4*)(A + (size_t)(m0+m)*lda + k0 + c);
            uint4 u = make_uint4(f2t(v.x), f2t(v.y), f2t(v.z), f2t(v.w));
            *(uint4*)(As + m*ASTR + c) = u;
        }
        #pragma unroll
        for (int p = 0; p < 2; p++) {       // B tile 16x128
            int idx = p*256 + tid;
            int kk = idx >> 5, c = (idx & 31) * 4;
            float4 v = *(const float4*)(Bw + (size_t)(k0+kk)*ldb + n0 + c);
            uint4 u = make_uint4(f2t(v.x), f2t(v.y), f2t(v.z), f2t(v.w));
            *(uint4*)(Bs + kk*BSTR + c) = u;
        }
        __syncthreads();

        #pragma unroll
        for (int kc = 0; kc < 2; kc++) {
            uint32_t af[2][4];
            #pragma unroll
            for (int mt = 0; mt < 2; mt++) {
                int mr = 32*wm + 16*mt + g;
                af[mt][0] = asp[(mr  )*ASTR + 8*kc + t4];
                af[mt][1] = asp[(mr+8)*ASTR + 8*kc + t4];
                af[mt][2] = asp[(mr  )*ASTR + 8*kc + t4 + 4];
                af[mt][3] = asp[(mr+8)*ASTR + 8*kc + t4 + 4];
            }
            #pragma unroll
            for (int nt = 0; nt < 8; nt++) {
                uint32_t bf[2];
                bf[0] = bsp[(8*kc+t4  )*BSTR + 64*wn + 8*nt + g];
                bf[1] = bsp[(8*kc+t4+4)*BSTR + 64*wn + 8*nt + g];
                mma8(acc[0][nt], af[0], bf);
                mma8(acc[1][nt], af[1], bf);
            }
        }
        __syncthreads();
    }
}

// ---------------------------------------------------------------------------
// Kernel 1: QKV projection. M=8192, N=1536, K=512. grid (12, 64).
// Epilogue: Q/K natural [b,h,l,d] (coalesced float2); V transposed [b,h,d,l].
// ---------------------------------------------------------------------------
__global__ __launch_bounds__(256) void qkv_gemm_kernel(
    const float* __restrict__ x, const float* __restrict__ wqkv,
    const float* __restrict__ bias)
{
    __shared__ float As[128*ASTR];
    __shared__ float Bs[16*BSTR];
    const int m0 = blockIdx.y * 128;
    const int n0 = blockIdx.x * 128;
    const int tid = threadIdx.x;
    const int lane = tid & 31;
    const int g = lane >> 2, t4 = lane & 3;
    const int w = tid >> 5;
    const int wm = w & 3, wn = w >> 2;

    float acc[2][8][4] = {};
    gemm_core(x, wqkv, Dm, 3*Dm, m0, n0, acc, As, Bs);

    const int nbase = n0 + 64*wn;
    const int h   = nbase / 192;
    const int sec = (nbase >> 6) % 3;       // 0=Q 1=K 2=V

    #pragma unroll
    for (int mt = 0; mt < 2; mt++) {
        #pragma unroll
        for (int rr = 0; rr < 2; rr++) {
            int m = m0 + 32*wm + 16*mt + g + 8*rr;
            int b = m >> 12, l = m & (Lq-1);
            #pragma unroll
            for (int nt = 0; nt < 8; nt++) {
                int nn = nbase + 8*nt + 2*t4;
                float v0 = acc[mt][nt][2*rr+0] + bias[nn];
                float v1 = acc[mt][nt][2*rr+1] + bias[nn+1];
                int d0 = nn & 63;
                if (sec == 2) {
                    // V transposed: [b][h][d][l]
                    g_v[((size_t)(b*Hn+h)*HD + d0  )*Lq + l] = __uint_as_float(f2t(v0));
                    g_v[((size_t)(b*Hn+h)*HD + d0+1)*Lq + l] = __uint_as_float(f2t(v1));
                } else {
                    float sc = (sec == 0) ? 0.125f : 1.0f;
                    float* dst = (sec == 0) ? g_q : g_k;
                    float2 o2;
                    o2.x = __uint_as_float(f2t(v0*sc));
                    o2.y = __uint_as_float(f2t(v1*sc));
                    *(float2*)(dst + ((size_t)(b*Hn+h)*Lq + l)*HD + d0) = o2;
                }
            }
        }
    }
}

// ---------------------------------------------------------------------------
// Kernel 2: flash attention, TF32 mma + ldmatrix fragment loads.
// grid (64, 16), 128 threads. Br=Bc=64, HD=64; warp w owns rows 16w..16w+15.
// Smem (static, 48KB): Ks[j][d], Vs[d][j], Ps[i][j], 64x64 each, chunk-swizzled:
//   SIDX(r,c): 16B chunk index cc=c>>2 xored with r&7 -> ldmatrix row-gathers
//   (8 rows x 16B) land on 8 distinct chunks = one 128B wavefront, conflict-free.
// Q tile staged through Ks, fragments hoisted via ldsm before the KV loop.
// ---------------------------------------------------------------------------
#define SIDX(r, c) (((r) << 6) + (((((c) >> 2) ^ ((r) & 7)) << 2)) + ((c) & 3))

__global__ __launch_bounds__(128) void flash_kernel()
{
    __shared__ float Ks[64*64];
    __shared__ float Vs[64*64];
    __shared__ float Ps[64*64];
    const int bh = blockIdx.y;
    const int i0 = blockIdx.x * 64;
    const int tid = threadIdx.x;
    const int w = tid >> 5, lane = tid & 31;
    const int g = lane >> 2, t4 = lane & 3;
    const int sel = lane >> 3, r8 = lane & 7;
    // ldsm per-lane address pattern for A-operands (a0..a3 = rows {0-7,8-15} x cols {0-3,4-7}):
    const int a_row = ((sel & 1) << 3) + r8;
    const int a_col = (sel >> 1) << 2;
    // ...and B-operands (R0,R1 = b0,b1 of n-block 0; R2,R3 = n-block 1):
    const int b_row = ((sel >> 1) << 3) + r8;
    const int b_col = (sel & 1) << 2;

    const float* qb = g_q + (size_t)bh*Lq*HD;   // [l][d]
    const float* kb = g_k + (size_t)bh*Lq*HD;   // [l][d]
    const float* vb = g_v + (size_t)bh*HD*Lq;   // [d][l]

    const uint32_t ks_b = smem_u32(Ks);
    const uint32_t vs_b = smem_u32(Vs);
    const uint32_t ps_b = smem_u32(Ps);

    // Stage Q tile [i][d] in Ks region, hoist A-fragments for the whole loop.
    #pragma unroll
    for (int p = 0; p < 8; p++) {
        int idx = p*128 + tid;
        int a = idx >> 4, c4 = (idx & 15) << 2;
        *(float4*)&Ks[SIDX(a, c4)] = *(const float4*)(qb + (size_t)(i0+a)*HD + c4);
    }
    __syncthreads();
    uint32_t qf[8][4];
    #pragma unroll
    for (int kc = 0; kc < 8; kc++)
        ldsm4(qf[kc], ks_b + 4u*SIDX(16*w + a_row, 8*kc + a_col));

    float of[8][4] = {};
    float mlo = -1e30f, mhi = -1e30f, llo = 0.f, lhi = 0.f;
    uint32_t* pw = (uint32_t*)Ps;
    const int row_lo = 16*w + g, row_hi = row_lo + 8;

    for (int j0 = 0; j0 < Lq; j0 += 64) {
        __syncthreads();                     // Q staging / prev K+V reads done
        #pragma unroll
        for (int p = 0; p < 8; p++) {
            int idx = p*128 + tid;
            int a = idx >> 4, c4 = (idx & 15) << 2;
            *(float4*)&Ks[SIDX(a, c4)] = *(const float4*)(kb + (size_t)(j0+a)*HD + c4);
            *(float4*)&Vs[SIDX(a, c4)] = *(const float4*)(vb + (size_t)a*Lq + j0 + c4);
        }
        __syncthreads();

        // S = Q K^T (16x64 per warp); B-frags via ldsm from Ks[j][d]
        float s[8][4] = {};
        #pragma unroll
        for (int kc = 0; kc < 8; kc++) {
            #pragma unroll
            for (int ntp = 0; ntp < 4; ntp++) {
                uint32_t bf[4];
                ldsm4(bf, ks_b + 4u*SIDX(16*ntp + b_row, 8*kc + b_col));
                mma8(s[2*ntp  ], qf[kc], bf);
                mma8(s[2*ntp+1], qf[kc], bf + 2);
            }
        }

        // Online softmax: row_lo holds (c0,c1), row_hi holds (c2,c3); quad-reduce.
        float mxl = -1e30f, mxh = -1e30f;
        #pragma unroll
        for (int nt = 0; nt < 8; nt++) {
            mxl = fmaxf(mxl, fmaxf(s[nt][0], s[nt][1]));
            mxh = fmaxf(mxh, fmaxf(s[nt][2], s[nt][3]));
        }
        mxl = fmaxf(mxl, __shfl_xor_sync(0xffffffffu, mxl, 1));
        mxl = fmaxf(mxl, __shfl_xor_sync(0xffffffffu, mxl, 2));
        mxh = fmaxf(mxh, __shfl_xor_sync(0xffffffffu, mxh, 1));
        mxh = fmaxf(mxh, __shfl_xor_sync(0xffffffffu, mxh, 2));
        float mnl = fmaxf(mxl, mlo), mnh = fmaxf(mxh, mhi);
        float al = __expf(mlo - mnl), ah = __expf(mhi - mnh);
        mlo = mnl; mhi = mnh;
        float sl = 0.f, sh = 0.f;
        #pragma unroll
        for (int nt = 0; nt < 8; nt++) {
            s[nt][0] = __expf(s[nt][0] - mnl);
            s[nt][1] = __expf(s[nt][1] - mnl);
            s[nt][2] = __expf(s[nt][2] - mnh);
            s[nt][3] = __expf(s[nt][3] - mnh);
            sl += s[nt][0] + s[nt][1];
            sh += s[nt][2] + s[nt][3];
        }
        sl += __shfl_xor_sync(0xffffffffu, sl, 1);
        sl += __shfl_xor_sync(0xffffffffu, sl, 2);
        sh += __shfl_xor_sync(0xffffffffu, sh, 1);
        sh += __shfl_xor_sync(0xffffffffu, sh, 2);
        llo = llo*al + sl; lhi = lhi*ah + sh;
        #pragma unroll
        for (int nt = 0; nt < 8; nt++) {
            of[nt][0] *= al; of[nt][1] *= al;
            of[nt][2] *= ah; of[nt][3] *= ah;
        }

        // P (tf32) -> warp-private smem rows [i][j] (c&3 in {0,2}: uint2 stays in-chunk)
        #pragma unroll
        for (int nt = 0; nt < 8; nt++) {
            uint2 lo = make_uint2(f2t(s[nt][0]), f2t(s[nt][1]));
            uint2 hi = make_uint2(f2t(s[nt][2]), f2t(s[nt][3]));
            *(uint2*)&pw[SIDX(row_lo, 8*nt + 2*t4)] = lo;
            *(uint2*)&pw[SIDX(row_hi, 8*nt + 2*t4)] = hi;
        }
        __syncwarp();

        // O += P @ V ; P A-frags + V B-frags via ldsm
        #pragma unroll
        for (int kc = 0; kc < 8; kc++) {
            uint32_t pf[4];
            ldsm4(pf, ps_b + 4u*SIDX(16*w + a_row, 8*kc + a_col));
            #pragma unroll
            for (int ntp = 0; ntp < 4; ntp++) {
                uint32_t bf[4];
                ldsm4(bf, vs_b + 4u*SIDX(16*ntp + b_row, 8*kc + b_col));
                mma8(of[2*ntp  ], pf, bf);
                mma8(of[2*ntp+1], pf, bf + 2);
            }
        }
        __syncwarp();
    }

    const int b = bh >> 3, h = bh & 7;
    float il = 1.0f/llo, ih = 1.0f/lhi;
    int rlo = i0 + row_lo, rhi = i0 + row_hi;
    #pragma unroll
    for (int nt = 0; nt < 8; nt++) {
        int d0 = h*64 + 8*nt + 2*t4;
        *(float2*)(g_o + ((size_t)b*Lq + rlo)*Dm + d0) = make_float2(of[nt][0]*il, of[nt][1]*il);
        *(float2*)(g_o + ((size_t)b*Lq + rhi)*Dm + d0) = make_float2(of[nt][2]*ih, of[nt][3]*ih);
    }
}

// ---------------------------------------------------------------------------
// Kernel 3: output projection. M=8192, N=512, K=512. grid (4, 64).
// ---------------------------------------------------------------------------
__global__ __launch_bounds__(256) void out_gemm_kernel(
    const float* __restrict__ wo, const float* __restrict__ bias,
    float* __restrict__ out)
{
    __shared__ float As[128*ASTR];
    __shared__ float Bs[16*BSTR];
    const int m0 = blockIdx.y * 128;
    const int n0 = blockIdx.x * 128;
    const int tid = threadIdx.x;
    const int lane = tid & 31;
    const int g = lane >> 2, t4 = lane & 3;
    const int w = tid >> 5;
    const int wm = w & 3, wn = w >> 2;

    float acc[2][8][4] = {};
    gemm_core(g_o, wo, Dm, Dm, m0, n0, acc, As, Bs);

    #pragma unroll
    for (int mt = 0; mt < 2; mt++) {
        #pragma unroll
        for (int rr = 0; rr < 2; rr++) {
            int m = m0 + 32*wm + 16*mt + g + 8*rr;
            #pragma unroll
            for (int nt = 0; nt < 8; nt++) {
                int n = n0 + 64*wn + 8*nt + 2*t4;
                float2 o2;
                o2.x = acc[mt][nt][2*rr+0] + bias[n];
                o2.y = acc[mt][nt][2*rr+1] + bias[n+1];
                *(float2*)(out + (size_t)m*Dm + n) = o2;
            }
        }
    }
}

extern "C" void kernel_launch(void* const* d_in, const int* in_sizes, int n_in,
                              void* d_out, int out_size)
{
    const float* x     = (const float*)d_in[0];
    const float* w_qkv = (const float*)d_in[1];
    const float* b_qkv = (const float*)d_in[2];
    const float* w_o   = (const float*)d_in[3];
    const float* b_o   = (const float*)d_in[4];
    float* out = (float*)d_out;

    dim3 g1(3*Dm/128, (Bsz*Lq)/128);   // (12, 64)
    qkv_gemm_kernel<<<g1, 256>>>(x, w_qkv, b_qkv);

    dim3 g2(Lq/64, Bsz*Hn);            // (64, 16)
    flash_kernel<<<g2, 128>>>();

    dim3 g3(Dm/128, (Bsz*Lq)/128);     // (4, 64)
    out_gemm_kernel<<<g3, 256>>>(w_o, b_o, out);
}